// round 14
// baseline (speedup 1.0000x reference)
#include <cuda_runtime.h>
#include <cuda_fp16.h>
#include <math.h>
#include <stdint.h>

// ---------------- problem constants ----------------
#define B_    8
#define T_    256
#define D_    512
#define W_    32
#define L_    4
#define A_    6
#define H_    8
#define DH    64
#define NSEQ  (B_*T_)        // 2048
#define MROWS (NSEQ*W_)      // 65536
#define D3    (3*D_)         // 1536
#define DF    (4*D_)         // 2048

#define BKH   64             // K halves per chunk (128B per row)
#define RS    72             // smem row stride in halves (144B, ldmatrix conflict-free)
#define BM    128
#define BN    256
#define ABYT  (BM*RS*2)      // 18432 B  A tile
#define BBYT  (BN*RS*2)      // 36864 B  B tile
#define STG   (ABYT+BBYT)    // 55296 B per stage
#define NSTAGE 3
#define HGEMM_SMEM (NSTAGE*STG)   // 165888 B

// converted-weight offsets (halves)
#define OFF_WQKV 0
#define OFF_WO   ((size_t)L_*D3*D_)
#define OFF_W1   (OFF_WO + (size_t)L_*D_*D_)
#define OFF_W2   (OFF_W1 + (size_t)L_*DF*D_)
#define WC_TOTAL (OFF_W2 + (size_t)L_*D_*DF)

// ---------------- scratch (device globals; no allocations) ----------------
__device__ __align__(16) __half g_X   [(size_t)MROWS * D_];   // fp16 activations
__device__ __align__(16) __half g_QKV [(size_t)MROWS * D3];   // fp16 qkv
__device__ __align__(16) __half g_H   [(size_t)MROWS * DF];   // fp16 ctx / ff hidden
__device__ __align__(16) float  g_PRE [(size_t)MROWS * D_];   // fp32 preLN
__device__ __align__(16) __half g_Wc  [WC_TOTAL];             // fp16 weights
__device__ __align__(16) __half g_feh [(size_t)NSEQ * D_];    // fp16 feats
__device__ __align__(16) __half g_F   [(size_t)NSEQ * D3];    // layer0: feats @ Wqkv0^T
__device__ __align__(16) __half g_posh[(size_t)128 * D_];     // fp16 pos (rows 0..31), rest zero
__device__ __align__(16) float  g_P   [(size_t)128 * D3];     // layer0: pos @ Wqkv0^T + bqkv0
__device__ float g_zerob[D3];                                 // zero bias (static zero-init)

// ---------------- PTX helpers ----------------
__device__ __forceinline__ uint32_t smem_u32(const void* p) {
    uint32_t a;
    asm("{ .reg .u64 t; cvta.to.shared.u64 t, %1; cvt.u32.u64 %0, t; }" : "=r"(a) : "l"(p));
    return a;
}
__device__ __forceinline__ void cp16(uint32_t s, const void* g) {
    asm volatile("cp.async.cg.shared.global [%0], [%1], 16;" :: "r"(s), "l"(g));
}
__device__ __forceinline__ void cp_commit() {
    asm volatile("cp.async.commit_group;" ::: "memory");
}
__device__ __forceinline__ void cp_wait1() { asm volatile("cp.async.wait_group 1;" ::: "memory"); }
__device__ __forceinline__ void cp_wait0() { asm volatile("cp.async.wait_group 0;" ::: "memory"); }

__device__ __forceinline__ void ldm_x4(uint32_t r[4], uint32_t addr) {
    asm volatile("ldmatrix.sync.aligned.m8n8.x4.shared.b16 {%0,%1,%2,%3}, [%4];"
                 : "=r"(r[0]), "=r"(r[1]), "=r"(r[2]), "=r"(r[3]) : "r"(addr));
}
__device__ __forceinline__ void mma_f16(float4& c, const uint32_t a[4], const uint32_t b0, const uint32_t b1) {
    asm volatile(
        "mma.sync.aligned.m16n8k16.row.col.f32.f16.f16.f32 "
        "{%0,%1,%2,%3}, {%4,%5,%6,%7}, {%8,%9}, {%0,%1,%2,%3};"
        : "+f"(c.x), "+f"(c.y), "+f"(c.z), "+f"(c.w)
        : "r"(a[0]), "r"(a[1]), "r"(a[2]), "r"(a[3]), "r"(b0), "r"(b1));
}

__device__ __forceinline__ void st2(float* p, float x, float y)  { *(float2*)p = make_float2(x, y); }
__device__ __forceinline__ void st2(__half* p, float x, float y) { *(__half2*)p = __floats2half2_rn(x, y); }

// ---------------- fp32 -> fp16 bulk conversion ----------------
__global__ __launch_bounds__(256)
void cvtw_k(const float* __restrict__ src, __half* __restrict__ dst, int n8)
{
    int i = blockIdx.x * 256 + threadIdx.x;
    if (i >= n8) return;
    const float4 a = *(const float4*)(src + (size_t)i * 8);
    const float4 b = *(const float4*)(src + (size_t)i * 8 + 4);
    __half2 h[4];
    h[0] = __floats2half2_rn(a.x, a.y);
    h[1] = __floats2half2_rn(a.z, a.w);
    h[2] = __floats2half2_rn(b.x, b.y);
    h[3] = __floats2half2_rn(b.z, b.w);
    *(uint2*)(dst + (size_t)i * 8)     = *(uint2*)&h[0];
    *(uint2*)(dst + (size_t)i * 8 + 4) = *(uint2*)&h[2];
}

// ---------------- build X = fp16(feats[window] + pos_embed) ----------------
__global__ __launch_bounds__(256)
void buildx_k(const float* __restrict__ feats, const float* __restrict__ pos)
{
    int idx = blockIdx.x * 256 + threadIdx.x;     // 8 halves per thread
    int d8  = idx & 63;
    int w   = (idx >> 6) & 31;
    int seq = idx >> 11;
    int t   = seq & (T_ - 1);
    int f   = t + 1 - W_ + w; if (f < 0) f = 0;
    int frame = (seq - t) + f;
    const float* fa = feats + (size_t)frame * D_ + d8 * 8;
    const float* pp = pos   + (size_t)w     * D_ + d8 * 8;
    float4 a0 = *(const float4*)fa, a1 = *(const float4*)(fa + 4);
    float4 p0 = *(const float4*)pp, p1 = *(const float4*)(pp + 4);
    __half2 h[4];
    h[0] = __floats2half2_rn(a0.x + p0.x, a0.y + p0.y);
    h[1] = __floats2half2_rn(a0.z + p0.z, a0.w + p0.w);
    h[2] = __floats2half2_rn(a1.x + p1.x, a1.y + p1.y);
    h[3] = __floats2half2_rn(a1.z + p1.z, a1.w + p1.w);
    __half* dst = g_X + (size_t)idx * 8;
    *(uint2*)dst       = *(uint2*)&h[0];
    *(uint2*)(dst + 4) = *(uint2*)&h[2];
}

// ---------------- layer-0 qkv gather: qkv = fp16(F[frame] + P[w]) ----------------
__global__ __launch_bounds__(256)
void qkv0_k(const __half* __restrict__ F, const float* __restrict__ P,
            __half* __restrict__ qkv)
{
    int idx = blockIdx.x * 256 + threadIdx.x;     // 8 halves per thread
    int n8  = idx % (D3 / 8);
    int row = idx / (D3 / 8);
    int w   = row & 31;
    int seq = row >> 5;
    int t   = seq & (T_ - 1);
    int f   = t + 1 - W_ + w; if (f < 0) f = 0;
    int frame = (seq - t) + f;
    const __half* fr = F + (size_t)frame * D3 + n8 * 8;
    const float*  pr = P + (size_t)w * D3 + n8 * 8;
    uint2 f01 = *(const uint2*)fr;
    uint2 f23 = *(const uint2*)(fr + 4);
    float4 pa = *(const float4*)pr;
    float4 pb = *(const float4*)(pr + 4);
    float2 a0 = __half22float2(*(__half2*)&f01.x);
    float2 a1 = __half22float2(*(__half2*)&f01.y);
    float2 a2 = __half22float2(*(__half2*)&f23.x);
    float2 a3 = __half22float2(*(__half2*)&f23.y);
    __half2 h[4];
    h[0] = __floats2half2_rn(a0.x + pa.x, a0.y + pa.y);
    h[1] = __floats2half2_rn(a1.x + pa.z, a1.y + pa.w);
    h[2] = __floats2half2_rn(a2.x + pb.x, a2.y + pb.y);
    h[3] = __floats2half2_rn(a3.x + pb.z, a3.y + pb.w);
    __half* dst = qkv + (size_t)idx * 8;
    *(uint2*)dst       = *(uint2*)&h[0];
    *(uint2*)(dst + 4) = *(uint2*)&h[2];
}

// ---------------- fp16 mma.sync GEMM (128x256 tile, warp 64x64, 3-stage, 1 barrier/chunk) -------
template<int RELU, typename TC>
__global__ __launch_bounds__(256, 1)
void hgemm_k(const __half* __restrict__ A, const __half* __restrict__ Bw,
             const float* __restrict__ bias, const __half* __restrict__ resid,
             TC* __restrict__ C, int M, int N, int K)
{
    extern __shared__ __half sh[];
    const uint32_t sm0 = smem_u32(sh);

    const int tid  = threadIdx.x;
    const int lane = tid & 31;
    const int wid  = tid >> 5;
    const int wm   = wid >> 2;          // 0..1 (64-row slab)
    const int wn   = wid & 3;           // 0..3 (64-col slab)
    const int l4   = lane >> 2;
    const int lm   = lane & 3;
    const int n0   = blockIdx.x * BN;
    const int m0   = blockIdx.y * BM;

    // staging: A 128 rows, B 256 rows, 128B per row
    const int row0 = tid >> 3;          // 0..31
    const int prt0 = tid & 7;           // 0..7
    const __half* Au = A  + (size_t)(m0 + row0) * K + prt0 * 8;
    const __half* Bu = Bw + (size_t)(n0 + row0) * K + prt0 * 8;
    const uint32_t du = (uint32_t)(row0 * RS + prt0 * 8) * 2;

    auto stage = [&](int c) {
        uint32_t base = sm0 + (uint32_t)(c % NSTAGE) * STG;
        const size_t ko = (size_t)c * BKH;
#pragma unroll
        for (int i = 0; i < 4; i++)
            cp16(base + du + i * 32 * RS * 2, Au + (size_t)(i * 32) * K + ko);
#pragma unroll
        for (int i = 0; i < 8; i++)
            cp16(base + ABYT + du + i * 32 * RS * 2, Bu + (size_t)(i * 32) * K + ko);
        cp_commit();
    };

    // ldmatrix lane address components
    const int rA   = lane & 15;
    const int kofA = (lane >> 4) * 8;
    const int rB   = lane & 7;
    const int kofB = ((lane >> 3) & 1) * 8;
    const int whB  = (lane >> 4) * 8;

    const uint32_t aoffs = (uint32_t)((wm * 64 + rA) * RS + kofA) * 2;
    const uint32_t boffs = (uint32_t)ABYT + (uint32_t)((wn * 64 + whB + rB) * RS + kofB) * 2;

    float4 acc[4][8];
#pragma unroll
    for (int i = 0; i < 4; i++)
#pragma unroll
        for (int j = 0; j < 8; j++) acc[i][j] = make_float4(0.f, 0.f, 0.f, 0.f);

    const int nchunk = K / BKH;
    stage(0); stage(1);

    for (int c = 0; c < nchunk; c++) {
        if (c + 1 < nchunk) cp_wait1();
        else                cp_wait0();
        __syncthreads();                       // single barrier per chunk
        if (c + 2 < nchunk) stage(c + 2);

        const uint32_t base = sm0 + (uint32_t)(c % NSTAGE) * STG;

#pragma unroll
        for (int ks = 0; ks < 4; ks++) {
            const uint32_t ko = (uint32_t)(ks * 16) * 2;
            uint32_t af[4][4], bf[4][4];
#pragma unroll
            for (int mt = 0; mt < 4; mt++)
                ldm_x4(af[mt], base + aoffs + (uint32_t)(mt * 16 * RS) * 2 + ko);
#pragma unroll
            for (int ntp = 0; ntp < 4; ntp++)
                ldm_x4(bf[ntp], base + boffs + (uint32_t)(ntp * 16 * RS) * 2 + ko);
#pragma unroll
            for (int mt = 0; mt < 4; mt++)
#pragma unroll
                for (int nt = 0; nt < 8; nt++)
                    mma_f16(acc[mt][nt], af[mt],
                            bf[nt >> 1][(nt & 1) * 2], bf[nt >> 1][(nt & 1) * 2 + 1]);
        }
    }

#pragma unroll
    for (int mt = 0; mt < 4; mt++) {
        const int m = m0 + wm * 64 + mt * 16 + l4;
#pragma unroll
        for (int nt = 0; nt < 8; nt++) {
            const int n = n0 + wn * 64 + nt * 8 + lm * 2;
            float4 cc = acc[mt][nt];
            float2 bv = *(const float2*)(bias + n);
            cc.x += bv.x; cc.y += bv.y;
            cc.z += bv.x; cc.w += bv.y;
            if (resid) {
                float2 r0 = __half22float2(*(const __half2*)(resid + (size_t)m * N + n));
                float2 r1 = __half22float2(*(const __half2*)(resid + (size_t)(m + 8) * N + n));
                cc.x += r0.x; cc.y += r0.y;
                cc.z += r1.x; cc.w += r1.y;
            }
            if (RELU) {
                cc.x = fmaxf(cc.x, 0.f); cc.y = fmaxf(cc.y, 0.f);
                cc.z = fmaxf(cc.z, 0.f); cc.w = fmaxf(cc.w, 0.f);
            }
            st2(C + (size_t)m * N + n,       cc.x, cc.y);
            st2(C + (size_t)(m + 8) * N + n, cc.z, cc.w);
        }
    }
}

// ---------------- attention: one warp per (seq, head); fp16 qkv in, fp16 ctx out ----------------
__global__ __launch_bounds__(32)
void attn_k(const __half* __restrict__ qkv, __half* __restrict__ ctx)
{
    const int sh   = blockIdx.x;
    const int seq  = sh >> 3;
    const int h    = sh & 7;
    const int lane = threadIdx.x;

    __shared__ float4 ks[W_][16], vs[W_][16];

    const __half* base = qkv + (size_t)seq * W_ * D3 + h * DH;

#pragma unroll
    for (int i = 0; i < 16; i++) {
        int idx = i * 32 + lane;
        int row = idx >> 4, c4 = idx & 15;
        const __half* src = base + (size_t)row * D3 + c4 * 4;
        __half2 k0 = *(const __half2*)(src + 512);
        __half2 k1 = *(const __half2*)(src + 514);
        __half2 v0 = *(const __half2*)(src + 1024);
        __half2 v1 = *(const __half2*)(src + 1026);
        float2 ka = __half22float2(k0), kb = __half22float2(k1);
        float2 va = __half22float2(v0), vb = __half22float2(v1);
        ks[row][c4] = make_float4(ka.x, ka.y, kb.x, kb.y);
        vs[row][c4] = make_float4(va.x, va.y, vb.x, vb.y);
    }
    float4 q[16];
    {
        const __half* qr = base + (size_t)lane * D3;
#pragma unroll
        for (int i = 0; i < 16; i++) {
            float2 a = __half22float2(*(const __half2*)(qr + i * 4));
            float2 b = __half22float2(*(const __half2*)(qr + i * 4 + 2));
            q[i] = make_float4(a.x, a.y, b.x, b.y);
        }
    }
    __syncwarp();

    float sc[W_];
#pragma unroll
    for (int c = 0; c < W_; c++) {
        float s = 0.f;
#pragma unroll
        for (int e = 0; e < 16; e++) {
            float4 kk = ks[c][e];
            s += q[e].x * kk.x + q[e].y * kk.y + q[e].z * kk.z + q[e].w * kk.w;
        }
        sc[c] = (c <= lane) ? s * 0.125f : -1e30f;
    }

    float mx = -1e30f;
#pragma unroll
    for (int c = 0; c < W_; c++) mx = fmaxf(mx, sc[c]);
    float sum = 0.f;
#pragma unroll
    for (int c = 0; c < W_; c++) { float e = expf(sc[c] - mx); sc[c] = e; sum += e; }
    float inv = 1.f / sum;

    float4 acc[16];
#pragma unroll
    for (int e = 0; e < 16; e++) acc[e] = make_float4(0.f, 0.f, 0.f, 0.f);
#pragma unroll
    for (int c = 0; c < W_; c++) {
        float p = sc[c] * inv;
#pragma unroll
        for (int e = 0; e < 16; e++) {
            float4 vv = vs[c][e];
            acc[e].x += p * vv.x; acc[e].y += p * vv.y;
            acc[e].z += p * vv.z; acc[e].w += p * vv.w;
        }
    }

    __half* dst = ctx + ((size_t)seq * W_ + lane) * D_ + h * DH;
#pragma unroll
    for (int e = 0; e < 16; e++) {
        *(__half2*)(dst + e * 4)     = __floats2half2_rn(acc[e].x, acc[e].y);
        *(__half2*)(dst + e * 4 + 2) = __floats2half2_rn(acc[e].z, acc[e].w);
    }
}

// ---------------- LayerNorm: warp per row; fp32 in -> fp16 out ----------------
__global__ __launch_bounds__(256)
void ln_k(const float* __restrict__ in, const float* __restrict__ g,
          const float* __restrict__ b, __half* __restrict__ out)
{
    const int row  = blockIdx.x * 8 + (threadIdx.x >> 5);
    const int lane = threadIdx.x & 31;
    const float* x = in + (size_t)row * D_ + lane * 4;

    float4 v[4];
#pragma unroll
    for (int i = 0; i < 4; i++) v[i] = *(const float4*)(x + i * 128);

    float s = 0.f, sq = 0.f;
#pragma unroll
    for (int i = 0; i < 4; i++) {
        s  += v[i].x + v[i].y + v[i].z + v[i].w;
        sq += v[i].x * v[i].x + v[i].y * v[i].y + v[i].z * v[i].z + v[i].w * v[i].w;
    }
#pragma unroll
    for (int off = 16; off; off >>= 1) {
        s  += __shfl_xor_sync(0xffffffffu, s,  off);
        sq += __shfl_xor_sync(0xffffffffu, sq, off);
    }
    const float mean = s * (1.f / D_);
    const float rstd = rsqrtf(sq * (1.f / D_) - mean * mean + 1e-5f);

    __half* o = out + (size_t)row * D_ + lane * 4;
#pragma unroll
    for (int i = 0; i < 4; i++) {
        float4 g4 = *(const float4*)(g + lane * 4 + i * 128);
        float4 b4 = *(const float4*)(b + lane * 4 + i * 128);
        float rx = (v[i].x - mean) * rstd * g4.x + b4.x;
        float ry = (v[i].y - mean) * rstd * g4.y + b4.y;
        float rz = (v[i].z - mean) * rstd * g4.z + b4.z;
        float rw = (v[i].w - mean) * rstd * g4.w + b4.w;
        *(__half2*)(o + i * 128)     = __floats2half2_rn(rx, ry);
        *(__half2*)(o + i * 128 + 2) = __floats2half2_rn(rz, rw);
    }
}

// ---------------- head: logits (B,T,A) then values (B,T) ----------------
__global__ __launch_bounds__(256)
void head_k(const __half* __restrict__ x, const float* __restrict__ Wp,
            const float* __restrict__ bp, const float* __restrict__ Wv,
            const float* __restrict__ bv, float* __restrict__ out)
{
    const int seq = blockIdx.x;
    __shared__ float tok[D_];
    const int tid = threadIdx.x;
    const __half* src = x + ((size_t)seq * W_ + (W_ - 1)) * D_;
    float2 f = __half22float2(*(const __half2*)(src + tid * 2));
    tok[tid * 2] = f.x; tok[tid * 2 + 1] = f.y;
    __syncthreads();
    int wid = tid >> 5, lane = tid & 31;
    if (wid < 7) {
        const float* wrow = (wid < 6) ? (Wp + wid * D_) : Wv;
        float s = 0.f;
        for (int i = lane; i < D_; i += 32) s += tok[i] * wrow[i];
#pragma unroll
        for (int off = 16; off; off >>= 1) s += __shfl_down_sync(0xffffffffu, s, off);
        if (lane == 0) {
            if (wid < 6) out[(size_t)seq * A_ + wid] = s + bp[wid];
            else         out[(size_t)NSEQ * A_ + seq] = s + bv[0];
        }
    }
}

// ---------------- launch ----------------
extern "C" void kernel_launch(void* const* d_in, const int* in_sizes, int n_in,
                              void* d_out, int out_size)
{
    const float* feats = (const float*)d_in[0];
    const float* pos   = (const float*)d_in[1];
    const float* Wqkv  = (const float*)d_in[2];
    const float* bqkv  = (const float*)d_in[3];
    const float* Wo    = (const float*)d_in[4];
    const float* bo    = (const float*)d_in[5];
    const float* ln1g  = (const float*)d_in[6];
    const float* ln1b  = (const float*)d_in[7];
    const float* W1    = (const float*)d_in[8];
    const float* b1    = (const float*)d_in[9];
    const float* W2    = (const float*)d_in[10];
    const float* b2    = (const float*)d_in[11];
    const float* ln2g  = (const float*)d_in[12];
    const float* ln2b  = (const float*)d_in[13];
    const float* Wp    = (const float*)d_in[14];
    const float* bp    = (const float*)d_in[15];
    const float* Wv    = (const float*)d_in[16];
    const float* bv    = (const float*)d_in[17];
    float* out = (float*)d_out;

    __half *X, *QKV, *Hb, *Wc, *FEH, *F, *POSH;
    float *PRE, *P, *ZB;
    cudaGetSymbolAddress((void**)&X,    g_X);
    cudaGetSymbolAddress((void**)&QKV,  g_QKV);
    cudaGetSymbolAddress((void**)&Hb,   g_H);
    cudaGetSymbolAddress((void**)&PRE,  g_PRE);
    cudaGetSymbolAddress((void**)&Wc,   g_Wc);
    cudaGetSymbolAddress((void**)&FEH,  g_feh);
    cudaGetSymbolAddress((void**)&F,    g_F);
    cudaGetSymbolAddress((void**)&POSH, g_posh);
    cudaGetSymbolAddress((void**)&P,    g_P);
    cudaGetSymbolAddress((void**)&ZB,   g_zerob);

    static int attr_done = 0;
    if (!attr_done) {
        cudaFuncSetAttribute(hgemm_k<0, float>,  cudaFuncAttributeMaxDynamicSharedMemorySize, HGEMM_SMEM);
        cudaFuncSetAttribute(hgemm_k<0, __half>, cudaFuncAttributeMaxDynamicSharedMemorySize, HGEMM_SMEM);
        cudaFuncSetAttribute(hgemm_k<1, __half>, cudaFuncAttributeMaxDynamicSharedMemorySize, HGEMM_SMEM);
        attr_done = 1;
    }

    // fp16 conversions: weights, feats, pos
    {
        int n;
        n = (int)((OFF_WO  - OFF_WQKV) / 8);
        cvtw_k<<<(n + 255) / 256, 256>>>(Wqkv, Wc + OFF_WQKV, n);
        n = (int)((OFF_W1  - OFF_WO) / 8);
        cvtw_k<<<(n + 255) / 256, 256>>>(Wo,   Wc + OFF_WO,   n);
        n = (int)((OFF_W2  - OFF_W1) / 8);
        cvtw_k<<<(n + 255) / 256, 256>>>(W1,   Wc + OFF_W1,   n);
        n = (int)((WC_TOTAL - OFF_W2) / 8);
        cvtw_k<<<(n + 255) / 256, 256>>>(W2,   Wc + OFF_W2,   n);
        n = NSEQ * D_ / 8;
        cvtw_k<<<(n + 255) / 256, 256>>>(feats, FEH, n);
        n = W_ * D_ / 8;
        cvtw_k<<<(n + 255) / 256, 256>>>(pos, POSH, n);
    }

    buildx_k<<<(MROWS * D_ / 8) / 256, 256>>>(feats, pos);

    for (int i = 0; i < L_; i++) {
        if (i == 0) {
            // layer-0 factorization: qkv = gather(F) + P
            hgemm_k<0, __half><<<dim3(D3 / BN, NSEQ / BM), 256, HGEMM_SMEM>>>(
                FEH, Wc + OFF_WQKV, ZB, nullptr, F, NSEQ, D3, D_);
            hgemm_k<0, float><<<dim3(D3 / BN, 1), 256, HGEMM_SMEM>>>(
                POSH, Wc + OFF_WQKV, bqkv, nullptr, P, 128, D3, D_);
            qkv0_k<<<(MROWS * D3 / 8) / 256, 256>>>(F, P, QKV);
        } else {
            hgemm_k<0, __half><<<dim3(D3 / BN, MROWS / BM), 256, HGEMM_SMEM>>>(
                X, Wc + OFF_WQKV + (size_t)i * D3 * D_, bqkv + i * D3, nullptr, QKV, MROWS, D3, D_);
        }
        // attention -> ctx (fp16)
        attn_k<<<NSEQ * H_, 32>>>(QKV, Hb);
        // preLN1(fp32) = X + ctx @ Wo^T + bo
        hgemm_k<0, float><<<dim3(D_ / BN, MROWS / BM), 256, HGEMM_SMEM>>>(
            Hb, Wc + OFF_WO + (size_t)i * D_ * D_, bo + i * D_, X, PRE, MROWS, D_, D_);
        ln_k<<<MROWS / 8, 256>>>(PRE, ln1g + i * D_, ln1b + i * D_, X);
        // h(fp16) = relu(X @ W1^T + b1)
        hgemm_k<1, __half><<<dim3(DF / BN, MROWS / BM), 256, HGEMM_SMEM>>>(
            X, Wc + OFF_W1 + (size_t)i * DF * D_, b1 + i * DF, nullptr, Hb, MROWS, DF, D_);
        // preLN2(fp32) = X + h @ W2^T + b2
        hgemm_k<0, float><<<dim3(D_ / BN, MROWS / BM), 256, HGEMM_SMEM>>>(
            Hb, Wc + OFF_W2 + (size_t)i * D_ * DF, b2 + i * D_, X, PRE, MROWS, D_, DF);
        ln_k<<<MROWS / 8, 256>>>(PRE, ln2g + i * D_, ln2b + i * D_, X);
    }

    head_k<<<NSEQ, 256>>>(X, Wp, bp, Wv, bv, out);
}

// round 15
// speedup vs baseline: 1.3227x; 1.3227x over previous
#include <cuda_runtime.h>
#include <cuda_fp16.h>
#include <math.h>
#include <stdint.h>

// ---------------- problem constants ----------------
#define B_    8
#define T_    256
#define D_    512
#define W_    32
#define L_    4
#define A_    6
#define H_    8
#define DH    64
#define NSEQ  (B_*T_)        // 2048
#define MROWS (NSEQ*W_)      // 65536
#define D3    (3*D_)         // 1536
#define DF    (4*D_)         // 2048

#define BKH   64             // K halves per chunk (128B per row)
#define RS    72             // smem row stride in halves (144B, ldmatrix conflict-free)
#define CHB   (128*RS*2)     // 18432 B per matrix tile
#define STG   (2*CHB)        // 36864 B per stage
#define NSTAGE 3
#define HGEMM_SMEM (NSTAGE*STG)   // 110592 B

// converted-weight offsets (halves)
#define OFF_WQKV 0
#define OFF_WO   ((size_t)L_*D3*D_)
#define OFF_W1   (OFF_WO + (size_t)L_*D_*D_)
#define OFF_W2   (OFF_W1 + (size_t)L_*DF*D_)
#define WC_TOTAL (OFF_W2 + (size_t)L_*D_*DF)

// ---------------- scratch (device globals; no allocations) ----------------
__device__ __align__(16) __half g_X   [(size_t)MROWS * D_];   // fp16 activations
__device__ __align__(16) __half g_QKV [(size_t)MROWS * D3];   // fp16 qkv / layer-3 KV
__device__ __align__(16) __half g_H   [(size_t)MROWS * DF];   // fp16 ctx / ff hidden
__device__ __align__(16) float  g_PRE [(size_t)MROWS * D_];   // fp32 preLN
__device__ __align__(16) __half g_Wc  [WC_TOTAL];             // fp16 weights
__device__ __align__(16) __half g_feh [(size_t)NSEQ * D_];    // fp16 feats (layer0) / Xc (layer3)
__device__ __align__(16) __half g_F   [(size_t)NSEQ * D3];    // layer0 F / layer3 Qc
__device__ __align__(16) __half g_posh[(size_t)128 * D_];     // fp16 pos (rows 0..31), rest zero
__device__ __align__(16) float  g_P   [(size_t)128 * D3];     // layer0: pos @ Wqkv0^T + bqkv0
__device__ float g_zerob[D3];                                 // zero bias (static zero-init)

// ---------------- PTX helpers ----------------
__device__ __forceinline__ uint32_t smem_u32(const void* p) {
    uint32_t a;
    asm("{ .reg .u64 t; cvta.to.shared.u64 t, %1; cvt.u32.u64 %0, t; }" : "=r"(a) : "l"(p));
    return a;
}
__device__ __forceinline__ void cp16(uint32_t s, const void* g) {
    asm volatile("cp.async.cg.shared.global [%0], [%1], 16;" :: "r"(s), "l"(g));
}
__device__ __forceinline__ void cp_commit() {
    asm volatile("cp.async.commit_group;" ::: "memory");
}
__device__ __forceinline__ void cp_wait1() { asm volatile("cp.async.wait_group 1;" ::: "memory"); }
__device__ __forceinline__ void cp_wait0() { asm volatile("cp.async.wait_group 0;" ::: "memory"); }

__device__ __forceinline__ void ldm_x4(uint32_t r[4], uint32_t addr) {
    asm volatile("ldmatrix.sync.aligned.m8n8.x4.shared.b16 {%0,%1,%2,%3}, [%4];"
                 : "=r"(r[0]), "=r"(r[1]), "=r"(r[2]), "=r"(r[3]) : "r"(addr));
}
__device__ __forceinline__ void mma_f16(float4& c, const uint32_t a[4], const uint32_t b0, const uint32_t b1) {
    asm volatile(
        "mma.sync.aligned.m16n8k16.row.col.f32.f16.f16.f32 "
        "{%0,%1,%2,%3}, {%4,%5,%6,%7}, {%8,%9}, {%0,%1,%2,%3};"
        : "+f"(c.x), "+f"(c.y), "+f"(c.z), "+f"(c.w)
        : "r"(a[0]), "r"(a[1]), "r"(a[2]), "r"(a[3]), "r"(b0), "r"(b1));
}

__device__ __forceinline__ void st2(float* p, float x, float y)  { *(float2*)p = make_float2(x, y); }
__device__ __forceinline__ void st2(__half* p, float x, float y) { *(__half2*)p = __floats2half2_rn(x, y); }

// ---------------- fp32 -> fp16 bulk conversion ----------------
__global__ __launch_bounds__(256)
void cvtw_k(const float* __restrict__ src, __half* __restrict__ dst, int n8)
{
    int i = blockIdx.x * 256 + threadIdx.x;
    if (i >= n8) return;
    const float4 a = *(const float4*)(src + (size_t)i * 8);
    const float4 b = *(const float4*)(src + (size_t)i * 8 + 4);
    __half2 h[4];
    h[0] = __floats2half2_rn(a.x, a.y);
    h[1] = __floats2half2_rn(a.z, a.w);
    h[2] = __floats2half2_rn(b.x, b.y);
    h[3] = __floats2half2_rn(b.z, b.w);
    *(uint2*)(dst + (size_t)i * 8)     = *(uint2*)&h[0];
    *(uint2*)(dst + (size_t)i * 8 + 4) = *(uint2*)&h[2];
}

// ---------------- build X = fp16(feats[window] + pos_embed) ----------------
__global__ __launch_bounds__(256)
void buildx_k(const float* __restrict__ feats, const float* __restrict__ pos)
{
    int idx = blockIdx.x * 256 + threadIdx.x;     // 8 halves per thread
    int d8  = idx & 63;
    int w   = (idx >> 6) & 31;
    int seq = idx >> 11;
    int t   = seq & (T_ - 1);
    int f   = t + 1 - W_ + w; if (f < 0) f = 0;
    int frame = (seq - t) + f;
    const float* fa = feats + (size_t)frame * D_ + d8 * 8;
    const float* pp = pos   + (size_t)w     * D_ + d8 * 8;
    float4 a0 = *(const float4*)fa, a1 = *(const float4*)(fa + 4);
    float4 p0 = *(const float4*)pp, p1 = *(const float4*)(pp + 4);
    __half2 h[4];
    h[0] = __floats2half2_rn(a0.x + p0.x, a0.y + p0.y);
    h[1] = __floats2half2_rn(a0.z + p0.z, a0.w + p0.w);
    h[2] = __floats2half2_rn(a1.x + p1.x, a1.y + p1.y);
    h[3] = __floats2half2_rn(a1.z + p1.z, a1.w + p1.w);
    __half* dst = g_X + (size_t)idx * 8;
    *(uint2*)dst       = *(uint2*)&h[0];
    *(uint2*)(dst + 4) = *(uint2*)&h[2];
}

// ---------------- layer-0 qkv gather: qkv = fp16(F[frame] + P[w]) ----------------
__global__ __launch_bounds__(256)
void qkv0_k(const __half* __restrict__ F, const float* __restrict__ P,
            __half* __restrict__ qkv)
{
    int idx = blockIdx.x * 256 + threadIdx.x;     // 8 halves per thread
    int n8  = idx % (D3 / 8);
    int row = idx / (D3 / 8);
    int w   = row & 31;
    int seq = row >> 5;
    int t   = seq & (T_ - 1);
    int f   = t + 1 - W_ + w; if (f < 0) f = 0;
    int frame = (seq - t) + f;
    const __half* fr = F + (size_t)frame * D3 + n8 * 8;
    const float*  pr = P + (size_t)w * D3 + n8 * 8;
    uint2 f01 = *(const uint2*)fr;
    uint2 f23 = *(const uint2*)(fr + 4);
    float4 pa = *(const float4*)pr;
    float4 pb = *(const float4*)(pr + 4);
    float2 a0 = __half22float2(*(__half2*)&f01.x);
    float2 a1 = __half22float2(*(__half2*)&f01.y);
    float2 a2 = __half22float2(*(__half2*)&f23.x);
    float2 a3 = __half22float2(*(__half2*)&f23.y);
    __half2 h[4];
    h[0] = __floats2half2_rn(a0.x + pa.x, a0.y + pa.y);
    h[1] = __floats2half2_rn(a1.x + pa.z, a1.y + pa.w);
    h[2] = __floats2half2_rn(a2.x + pb.x, a2.y + pb.y);
    h[3] = __floats2half2_rn(a3.x + pb.z, a3.y + pb.w);
    __half* dst = qkv + (size_t)idx * 8;
    *(uint2*)dst       = *(uint2*)&h[0];
    *(uint2*)(dst + 4) = *(uint2*)&h[2];
}

// ---------------- gather w=31 rows of X into compact Xc (2048 x 512) ----------------
__global__ __launch_bounds__(256)
void gather31_k(const __half* __restrict__ X, __half* __restrict__ Xc)
{
    int idx = blockIdx.x * 256 + threadIdx.x;     // 8 halves; total NSEQ*64
    int d8  = idx & 63;
    int seq = idx >> 6;
    const __half* src = X + ((size_t)(seq * W_ + (W_ - 1))) * D_ + d8 * 8;
    __half* dst = Xc + (size_t)seq * D_ + d8 * 8;
    *(uint2*)dst       = *(const uint2*)src;
    *(uint2*)(dst + 4) = *(const uint2*)(src + 4);
}

// ---------------- fp16 mma.sync GEMM (128x128 tile, BK=64, 3-stage, 1 barrier/chunk) ----------------
template<int RELU, typename TC>
__global__ __launch_bounds__(256, 2)
void hgemm_k(const __half* __restrict__ A, const __half* __restrict__ Bw,
             const float* __restrict__ bias, const __half* __restrict__ resid,
             TC* __restrict__ C, int M, int N, int K)
{
    extern __shared__ __half sh[];
    const uint32_t sm0 = smem_u32(sh);

    const int tid  = threadIdx.x;
    const int lane = tid & 31;
    const int wid  = tid >> 5;
    const int wm   = wid >> 2;
    const int wn   = wid & 3;
    const int l4   = lane >> 2;
    const int lm   = lane & 3;
    const int n0   = blockIdx.x * 128;
    const int m0   = blockIdx.y * 128;

    const int row0 = tid >> 3;          // 0..31
    const int prt0 = tid & 7;           // 0..7
    const __half* Au = A  + (size_t)(m0 + row0) * K + prt0 * 8;
    const __half* Bu = Bw + (size_t)(n0 + row0) * K + prt0 * 8;
    const uint32_t du = (uint32_t)(row0 * RS + prt0 * 8) * 2;

    auto stage = [&](int c) {
        uint32_t base = sm0 + (uint32_t)(c % NSTAGE) * STG;
        const size_t ko = (size_t)c * BKH;
#pragma unroll
        for (int i = 0; i < 4; i++) {
            cp16(base + du + i * 32 * RS * 2,       Au + (size_t)(i * 32) * K + ko);
            cp16(base + CHB + du + i * 32 * RS * 2, Bu + (size_t)(i * 32) * K + ko);
        }
        cp_commit();
    };

    const int rA   = lane & 15;
    const int kofA = (lane >> 4) * 8;
    const int rB   = lane & 7;
    const int kofB = ((lane >> 3) & 1) * 8;
    const int whB  = (lane >> 4) * 8;

    const uint32_t aoffs = (uint32_t)((wm * 64 + rA) * RS + kofA) * 2;
    const uint32_t boffs = (uint32_t)CHB + (uint32_t)((wn * 32 + whB + rB) * RS + kofB) * 2;

    float4 acc[4][4];
#pragma unroll
    for (int i = 0; i < 4; i++)
#pragma unroll
        for (int j = 0; j < 4; j++) acc[i][j] = make_float4(0.f, 0.f, 0.f, 0.f);

    const int nchunk = K / BKH;
    stage(0); stage(1);

    uint32_t af[2][4][4], bf[2][2][4];

    for (int c = 0; c < nchunk; c++) {
        if (c + 1 < nchunk) cp_wait1();
        else                cp_wait0();
        __syncthreads();                       // single barrier per chunk
        if (c + 2 < nchunk) stage(c + 2);

        const uint32_t base = sm0 + (uint32_t)(c % NSTAGE) * STG;

        // prefetch ks=0 fragments
#pragma unroll
        for (int mt = 0; mt < 4; mt++)
            ldm_x4(af[0][mt], base + aoffs + (uint32_t)(mt * 16 * RS) * 2);
#pragma unroll
        for (int ntp = 0; ntp < 2; ntp++)
            ldm_x4(bf[0][ntp], base + boffs + (uint32_t)(ntp * 16 * RS) * 2);

#pragma unroll
        for (int ks = 0; ks < 4; ks++) {
            const int cur = ks & 1, nxt = cur ^ 1;
            if (ks < 3) {                      // prefetch next k-step under current MMAs
                const uint32_t ko = (uint32_t)((ks + 1) * 16) * 2;
#pragma unroll
                for (int mt = 0; mt < 4; mt++)
                    ldm_x4(af[nxt][mt], base + aoffs + (uint32_t)(mt * 16 * RS) * 2 + ko);
#pragma unroll
                for (int ntp = 0; ntp < 2; ntp++)
                    ldm_x4(bf[nxt][ntp], base + boffs + (uint32_t)(ntp * 16 * RS) * 2 + ko);
            }
#pragma unroll
            for (int mt = 0; mt < 4; mt++)
#pragma unroll
                for (int nt = 0; nt < 4; nt++)
                    mma_f16(acc[mt][nt], af[cur][mt],
                            bf[cur][nt >> 1][(nt & 1) * 2], bf[cur][nt >> 1][(nt & 1) * 2 + 1]);
        }
    }

    __syncthreads();

#pragma unroll
    for (int mt = 0; mt < 4; mt++) {
        const int m = m0 + wm * 64 + mt * 16 + l4;
#pragma unroll
        for (int nt = 0; nt < 4; nt++) {
            const int n = n0 + wn * 32 + nt * 8 + lm * 2;
            float4 cc = acc[mt][nt];
            float2 bv = *(const float2*)(bias + n);
            cc.x += bv.x; cc.y += bv.y;
            cc.z += bv.x; cc.w += bv.y;
            if (resid) {
                float2 r0 = __half22float2(*(const __half2*)(resid + (size_t)m * N + n));
                float2 r1 = __half22float2(*(const __half2*)(resid + (size_t)(m + 8) * N + n));
                cc.x += r0.x; cc.y += r0.y;
                cc.z += r1.x; cc.w += r1.y;
            }
            if (RELU) {
                cc.x = fmaxf(cc.x, 0.f); cc.y = fmaxf(cc.y, 0.f);
                cc.z = fmaxf(cc.z, 0.f); cc.w = fmaxf(cc.w, 0.f);
            }
            st2(C + (size_t)m * N + n,       cc.x, cc.y);
            st2(C + (size_t)(m + 8) * N + n, cc.z, cc.w);
        }
    }
}

// ---------------- attention (layers 0-2): one warp per (seq, head) ----------------
__global__ __launch_bounds__(32)
void attn_k(const __half* __restrict__ qkv, __half* __restrict__ ctx)
{
    const int sh   = blockIdx.x;
    const int seq  = sh >> 3;
    const int h    = sh & 7;
    const int lane = threadIdx.x;

    __shared__ float4 ks[W_][16], vs[W_][16];

    const __half* base = qkv + (size_t)seq * W_ * D3 + h * DH;

#pragma unroll
    for (int i = 0; i < 16; i++) {
        int idx = i * 32 + lane;
        int row = idx >> 4, c4 = idx & 15;
        const __half* src = base + (size_t)row * D3 + c4 * 4;
        __half2 k0 = *(const __half2*)(src + 512);
        __half2 k1 = *(const __half2*)(src + 514);
        __half2 v0 = *(const __half2*)(src + 1024);
        __half2 v1 = *(const __half2*)(src + 1026);
        float2 ka = __half22float2(k0), kb = __half22float2(k1);
        float2 va = __half22float2(v0), vb = __half22float2(v1);
        ks[row][c4] = make_float4(ka.x, ka.y, kb.x, kb.y);
        vs[row][c4] = make_float4(va.x, va.y, vb.x, vb.y);
    }
    float4 q[16];
    {
        const __half* qr = base + (size_t)lane * D3;
#pragma unroll
        for (int i = 0; i < 16; i++) {
            float2 a = __half22float2(*(const __half2*)(qr + i * 4));
            float2 b = __half22float2(*(const __half2*)(qr + i * 4 + 2));
            q[i] = make_float4(a.x, a.y, b.x, b.y);
        }
    }
    __syncwarp();

    float sc[W_];
#pragma unroll
    for (int c = 0; c < W_; c++) {
        float s = 0.f;
#pragma unroll
        for (int e = 0; e < 16; e++) {
            float4 kk = ks[c][e];
            s += q[e].x * kk.x + q[e].y * kk.y + q[e].z * kk.z + q[e].w * kk.w;
        }
        sc[c] = (c <= lane) ? s * 0.125f : -1e30f;
    }

    float mx = -1e30f;
#pragma unroll
    for (int c = 0; c < W_; c++) mx = fmaxf(mx, sc[c]);
    float sum = 0.f;
#pragma unroll
    for (int c = 0; c < W_; c++) { float e = expf(sc[c] - mx); sc[c] = e; sum += e; }
    float inv = 1.f / sum;

    float4 acc[16];
#pragma unroll
    for (int e = 0; e < 16; e++) acc[e] = make_float4(0.f, 0.f, 0.f, 0.f);
#pragma unroll
    for (int c = 0; c < W_; c++) {
        float p = sc[c] * inv;
#pragma unroll
        for (int e = 0; e < 16; e++) {
            float4 vv = vs[c][e];
            acc[e].x += p * vv.x; acc[e].y += p * vv.y;
            acc[e].z += p * vv.z; acc[e].w += p * vv.w;
        }
    }

    __half* dst = ctx + ((size_t)seq * W_ + lane) * D_ + h * DH;
#pragma unroll
    for (int e = 0; e < 16; e++) {
        *(__half2*)(dst + e * 4)     = __floats2half2_rn(acc[e].x, acc[e].y);
        *(__half2*)(dst + e * 4 + 2) = __floats2half2_rn(acc[e].z, acc[e].w);
    }
}

// ---------------- layer-3 attention: only row w=31; kv row stride 1024 ----------------
__global__ __launch_bounds__(32)
void attn3_k(const __half* __restrict__ kv, const __half* __restrict__ qc,
             __half* __restrict__ ctxc)
{
    const int sh   = blockIdx.x;
    const int seq  = sh >> 3;
    const int h    = sh & 7;
    const int lane = threadIdx.x;

    __shared__ float qs[DH];
    __shared__ float ps[W_];

    const __half* qp = qc + (size_t)seq * D_ + h * DH;
    float2 qv = __half22float2(*(const __half2*)(qp + lane * 2));
    qs[lane * 2] = qv.x; qs[lane * 2 + 1] = qv.y;
    __syncwarp();

    // score for column = lane (row 31 attends all 32 columns)
    const __half* kp = kv + ((size_t)seq * W_ + lane) * 1024 + h * DH;
    float s = 0.f;
#pragma unroll
    for (int e = 0; e < DH; e += 2) {
        float2 kk = __half22float2(*(const __half2*)(kp + e));
        s += qs[e] * kk.x + qs[e + 1] * kk.y;
    }
    s *= 0.125f;

    float mx = s;
#pragma unroll
    for (int o = 16; o; o >>= 1) mx = fmaxf(mx, __shfl_xor_sync(0xffffffffu, mx, o));
    float e = expf(s - mx), sum = e;
#pragma unroll
    for (int o = 16; o; o >>= 1) sum += __shfl_xor_sync(0xffffffffu, sum, o);
    ps[lane] = e / sum;
    __syncwarp();

    // ctx: lane covers d = lane*2, lane*2+1
    float a0 = 0.f, a1 = 0.f;
    const __half* vp = kv + (size_t)seq * W_ * 1024 + 512 + h * DH + lane * 2;
#pragma unroll
    for (int c = 0; c < W_; c++) {
        float2 vv = __half22float2(*(const __half2*)(vp + (size_t)c * 1024));
        a0 += ps[c] * vv.x; a1 += ps[c] * vv.y;
    }
    *(__half2*)(ctxc + (size_t)seq * D_ + h * DH + lane * 2) = __floats2half2_rn(a0, a1);
}

// ---------------- LayerNorm: warp per row; fp32 in -> fp16 out ----------------
__global__ __launch_bounds__(256)
void ln_k(const float* __restrict__ in, const float* __restrict__ g,
          const float* __restrict__ b, __half* __restrict__ out)
{
    const int row  = blockIdx.x * 8 + (threadIdx.x >> 5);
    const int lane = threadIdx.x & 31;
    const float* x = in + (size_t)row * D_ + lane * 4;

    float4 v[4];
#pragma unroll
    for (int i = 0; i < 4; i++) v[i] = *(const float4*)(x + i * 128);

    float s = 0.f, sq = 0.f;
#pragma unroll
    for (int i = 0; i < 4; i++) {
        s  += v[i].x + v[i].y + v[i].z + v[i].w;
        sq += v[i].x * v[i].x + v[i].y * v[i].y + v[i].z * v[i].z + v[i].w * v[i].w;
    }
#pragma unroll
    for (int off = 16; off; off >>= 1) {
        s  += __shfl_xor_sync(0xffffffffu, s,  off);
        sq += __shfl_xor_sync(0xffffffffu, sq, off);
    }
    const float mean = s * (1.f / D_);
    const float rstd = rsqrtf(sq * (1.f / D_) - mean * mean + 1e-5f);

    __half* o = out + (size_t)row * D_ + lane * 4;
#pragma unroll
    for (int i = 0; i < 4; i++) {
        float4 g4 = *(const float4*)(g + lane * 4 + i * 128);
        float4 b4 = *(const float4*)(b + lane * 4 + i * 128);
        float rx = (v[i].x - mean) * rstd * g4.x + b4.x;
        float ry = (v[i].y - mean) * rstd * g4.y + b4.y;
        float rz = (v[i].z - mean) * rstd * g4.z + b4.z;
        float rw = (v[i].w - mean) * rstd * g4.w + b4.w;
        *(__half2*)(o + i * 128)     = __floats2half2_rn(rx, ry);
        *(__half2*)(o + i * 128 + 2) = __floats2half2_rn(rz, rw);
    }
}

// ---------------- head: logits (B,T,A) then values (B,T); reads compact Xc ----------------
__global__ __launch_bounds__(256)
void head_k(const __half* __restrict__ xc, const float* __restrict__ Wp,
            const float* __restrict__ bp, const float* __restrict__ Wv,
            const float* __restrict__ bv, float* __restrict__ out)
{
    const int seq = blockIdx.x;
    __shared__ float tok[D_];
    const int tid = threadIdx.x;
    const __half* src = xc + (size_t)seq * D_;
    float2 f = __half22float2(*(const __half2*)(src + tid * 2));
    tok[tid * 2] = f.x; tok[tid * 2 + 1] = f.y;
    __syncthreads();
    int wid = tid >> 5, lane = tid & 31;
    if (wid < 7) {
        const float* wrow = (wid < 6) ? (Wp + wid * D_) : Wv;
        float s = 0.f;
        for (int i = lane; i < D_; i += 32) s += tok[i] * wrow[i];
#pragma unroll
        for (int off = 16; off; off >>= 1) s += __shfl_down_sync(0xffffffffu, s, off);
        if (lane == 0) {
            if (wid < 6) out[(size_t)seq * A_ + wid] = s + bp[wid];
            else         out[(size_t)NSEQ * A_ + seq] = s + bv[0];
        }
    }
}

// ---------------- launch ----------------
extern "C" void kernel_launch(void* const* d_in, const int* in_sizes, int n_in,
                              void* d_out, int out_size)
{
    const float* feats = (const float*)d_in[0];
    const float* pos   = (const float*)d_in[1];
    const float* Wqkv  = (const float*)d_in[2];
    const float* bqkv  = (const float*)d_in[3];
    const float* Wo    = (const float*)d_in[4];
    const float* bo    = (const float*)d_in[5];
    const float* ln1g  = (const float*)d_in[6];
    const float* ln1b  = (const float*)d_in[7];
    const float* W1    = (const float*)d_in[8];
    const float* b1    = (const float*)d_in[9];
    const float* W2    = (const float*)d_in[10];
    const float* b2    = (const float*)d_in[11];
    const float* ln2g  = (const float*)d_in[12];
    const float* ln2b  = (const float*)d_in[13];
    const float* Wp    = (const float*)d_in[14];
    const float* bp    = (const float*)d_in[15];
    const float* Wv    = (const float*)d_in[16];
    const float* bv    = (const float*)d_in[17];
    float* out = (float*)d_out;

    __half *X, *QKV, *Hb, *Wc, *FEH, *F, *POSH;
    float *PRE, *P, *ZB;
    cudaGetSymbolAddress((void**)&X,    g_X);
    cudaGetSymbolAddress((void**)&QKV,  g_QKV);
    cudaGetSymbolAddress((void**)&Hb,   g_H);
    cudaGetSymbolAddress((void**)&PRE,  g_PRE);
    cudaGetSymbolAddress((void**)&Wc,   g_Wc);
    cudaGetSymbolAddress((void**)&FEH,  g_feh);
    cudaGetSymbolAddress((void**)&F,    g_F);
    cudaGetSymbolAddress((void**)&POSH, g_posh);
    cudaGetSymbolAddress((void**)&P,    g_P);
    cudaGetSymbolAddress((void**)&ZB,   g_zerob);

    // layer-3 compact buffers (reuse scratch whose producers are done by then)
    __half* Xc   = FEH;   // 2048 x 512
    __half* Qc   = F;     // 2048 x 512
    __half* CTXc = Hb;    // 2048 x 512
    __half* HIDc = Hb;    // 2048 x 2048 (after CTXc consumed)
    __half* KV   = QKV;   // 65536 x 1024

    static int attr_done = 0;
    if (!attr_done) {
        cudaFuncSetAttribute(hgemm_k<0, float>,  cudaFuncAttributeMaxDynamicSharedMemorySize, HGEMM_SMEM);
        cudaFuncSetAttribute(hgemm_k<0, __half>, cudaFuncAttributeMaxDynamicSharedMemorySize, HGEMM_SMEM);
        cudaFuncSetAttribute(hgemm_k<1, __half>, cudaFuncAttributeMaxDynamicSharedMemorySize, HGEMM_SMEM);
        attr_done = 1;
    }

    // fp16 conversions: weights, feats, pos
    {
        int n;
        n = (int)((OFF_WO  - OFF_WQKV) / 8);
        cvtw_k<<<(n + 255) / 256, 256>>>(Wqkv, Wc + OFF_WQKV, n);
        n = (int)((OFF_W1  - OFF_WO) / 8);
        cvtw_k<<<(n + 255) / 256, 256>>>(Wo,   Wc + OFF_WO,   n);
        n = (int)((OFF_W2  - OFF_W1) / 8);
        cvtw_k<<<(n + 255) / 256, 256>>>(W1,   Wc + OFF_W1,   n);
        n = (int)((WC_TOTAL - OFF_W2) / 8);
        cvtw_k<<<(n + 255) / 256, 256>>>(W2,   Wc + OFF_W2,   n);
        n = NSEQ * D_ / 8;
        cvtw_k<<<(n + 255) / 256, 256>>>(feats, FEH, n);
        n = W_ * D_ / 8;
        cvtw_k<<<(n + 255) / 256, 256>>>(pos, POSH, n);
    }

    buildx_k<<<(MROWS * D_ / 8) / 256, 256>>>(feats, pos);

    // ---- layers 0..2: full pipeline ----
    for (int i = 0; i < L_ - 1; i++) {
        if (i == 0) {
            hgemm_k<0, __half><<<dim3(D3 / 128, NSEQ / 128), 256, HGEMM_SMEM>>>(
                FEH, Wc + OFF_WQKV, ZB, nullptr, F, NSEQ, D3, D_);
            hgemm_k<0, float><<<dim3(D3 / 128, 1), 256, HGEMM_SMEM>>>(
                POSH, Wc + OFF_WQKV, bqkv, nullptr, P, 128, D3, D_);
            qkv0_k<<<(MROWS * D3 / 8) / 256, 256>>>(F, P, QKV);
        } else {
            hgemm_k<0, __half><<<dim3(D3 / 128, MROWS / 128), 256, HGEMM_SMEM>>>(
                X, Wc + OFF_WQKV + (size_t)i * D3 * D_, bqkv + i * D3, nullptr, QKV, MROWS, D3, D_);
        }
        attn_k<<<NSEQ * H_, 32>>>(QKV, Hb);
        hgemm_k<0, float><<<dim3(D_ / 128, MROWS / 128), 256, HGEMM_SMEM>>>(
            Hb, Wc + OFF_WO + (size_t)i * D_ * D_, bo + i * D_, X, PRE, MROWS, D_, D_);
        ln_k<<<MROWS / 8, 256>>>(PRE, ln1g + i * D_, ln1b + i * D_, X);
        hgemm_k<1, __half><<<dim3(DF / 128, MROWS / 128), 256, HGEMM_SMEM>>>(
            X, Wc + OFF_W1 + (size_t)i * DF * D_, b1 + i * DF, nullptr, Hb, MROWS, DF, D_);
        hgemm_k<0, float><<<dim3(D_ / 128, MROWS / 128), 256, HGEMM_SMEM>>>(
            Hb, Wc + OFF_W2 + (size_t)i * D_ * DF, b2 + i * D_, X, PRE, MROWS, D_, DF);
        ln_k<<<MROWS / 8, 256>>>(PRE, ln2g + i * D_, ln2b + i * D_, X);
    }

    // ---- layer 3: only the w=31 rows survive into the head ----
    {
        const int i = L_ - 1;    // 3
        // K,V for all rows (weight rows 512..1535 of Wqkv[3])
        hgemm_k<0, __half><<<dim3(1024 / 128, MROWS / 128), 256, HGEMM_SMEM>>>(
            X, Wc + OFF_WQKV + (size_t)i * D3 * D_ + (size_t)D_ * D_,
            bqkv + i * D3 + D_, nullptr, KV, MROWS, 1024, D_);
        // compact X rows (w=31)
        gather31_k<<<(NSEQ * 64) / 256, 256>>>(X, Xc);
        // Q only for compact rows
        hgemm_k<0, __half><<<dim3(D_ / 128, NSEQ / 128), 256, HGEMM_SMEM>>>(
            Xc, Wc + OFF_WQKV + (size_t)i * D3 * D_, bqkv + i * D3, nullptr, Qc, NSEQ, D_, D_);
        // last-row attention
        attn3_k<<<NSEQ * H_, 32>>>(KV, Qc, CTXc);
        // Wo + resid -> preLN1 (compact)
        hgemm_k<0, float><<<dim3(D_ / 128, NSEQ / 128), 256, HGEMM_SMEM>>>(
            CTXc, Wc + OFF_WO + (size_t)i * D_ * D_, bo + i * D_, Xc, PRE, NSEQ, D_, D_);
        ln_k<<<NSEQ / 8, 256>>>(PRE, ln1g + i * D_, ln1b + i * D_, Xc);
        // FF (compact)
        hgemm_k<1, __half><<<dim3(DF / 128, NSEQ / 128), 256, HGEMM_SMEM>>>(
            Xc, Wc + OFF_W1 + (size_t)i * DF * D_, b1 + i * DF, nullptr, HIDc, NSEQ, DF, D_);
        hgemm_k<0, float><<<dim3(D_ / 128, NSEQ / 128), 256, HGEMM_SMEM>>>(
            HIDc, Wc + OFF_W2 + (size_t)i * D_ * DF, b2 + i * D_, Xc, PRE, NSEQ, D_, DF);
        ln_k<<<NSEQ / 8, 256>>>(PRE, ln2g + i * D_, ln2b + i * D_, Xc);
    }

    head_k<<<NSEQ, 256>>>(Xc, Wp, bp, Wv, bv, out);
}

// round 16
// speedup vs baseline: 1.3268x; 1.0031x over previous
#include <cuda_runtime.h>
#include <cuda_fp16.h>
#include <math.h>
#include <stdint.h>

// ---------------- problem constants ----------------
#define B_    8
#define T_    256
#define D_    512
#define W_    32
#define L_    4
#define A_    6
#define H_    8
#define DH    64
#define NSEQ  (B_*T_)        // 2048
#define MROWS (NSEQ*W_)      // 65536
#define D3    (3*D_)         // 1536
#define DF    (4*D_)         // 2048
#define MFP   2176           // stacked layer-0 rows: 2048 feats + 128 pos

#define BKH   64             // K halves per chunk (128B per row)
#define RS    72             // smem row stride in halves (144B, ldmatrix conflict-free)
#define CHB   (128*RS*2)     // 18432 B per matrix tile
#define STG   (2*CHB)        // 36864 B per stage
#define NSTAGE 3
#define HGEMM_SMEM (NSTAGE*STG)   // 110592 B

// converted-weight offsets (halves) — order matches cvtall segments
#define OFF_WQKV 0
#define OFF_WO   ((size_t)L_*D3*D_)
#define OFF_W1   (OFF_WO + (size_t)L_*D_*D_)
#define OFF_W2   (OFF_W1 + (size_t)L_*DF*D_)
#define WC_TOTAL (OFF_W2 + (size_t)L_*D_*DF)

#define N8_WQKV (L_*D3*D_/8)     // 393216
#define N8_WO   (L_*D_*D_/8)     // 131072
#define N8_W1   (L_*DF*D_/8)     // 524288
#define N8_W2   (L_*D_*DF/8)     // 524288
#define N8_WTOT (N8_WQKV+N8_WO+N8_W1+N8_W2)   // 1572864
#define N8_FE   (NSEQ*D_/8)      // 131072
#define N8_PO   (W_*D_/8)        // 2048

// ---------------- scratch (device globals; no allocations) ----------------
__device__ __align__(16) __half g_X   [(size_t)MROWS * D_];   // fp16 activations
__device__ __align__(16) __half g_QKV [(size_t)MROWS * D3];   // fp16 qkv / layer-3 KV
__device__ __align__(16) __half g_H   [(size_t)MROWS * DF];   // fp16 ctx / ff hidden
__device__ __align__(16) float  g_PRE [(size_t)MROWS * D_];   // fp32 preLN
__device__ __align__(16) __half g_Wc  [WC_TOTAL];             // fp16 weights
__device__ __align__(16) __half g_FP  [(size_t)MFP * D_];     // stacked feats(2048)+pos(32), rest 0
__device__ __align__(16) __half g_F   [(size_t)MFP * D3];     // layer0 F/P out; layer3 Qc
__device__ float g_zerob[D3];                                 // zero bias (static zero-init)

// ---------------- PTX helpers ----------------
__device__ __forceinline__ uint32_t smem_u32(const void* p) {
    uint32_t a;
    asm("{ .reg .u64 t; cvta.to.shared.u64 t, %1; cvt.u32.u64 %0, t; }" : "=r"(a) : "l"(p));
    return a;
}
__device__ __forceinline__ void cp16(uint32_t s, const void* g) {
    asm volatile("cp.async.cg.shared.global [%0], [%1], 16;" :: "r"(s), "l"(g));
}
__device__ __forceinline__ void cp_commit() {
    asm volatile("cp.async.commit_group;" ::: "memory");
}
__device__ __forceinline__ void cp_wait1() { asm volatile("cp.async.wait_group 1;" ::: "memory"); }
__device__ __forceinline__ void cp_wait0() { asm volatile("cp.async.wait_group 0;" ::: "memory"); }

__device__ __forceinline__ void ldm_x4(uint32_t r[4], uint32_t addr) {
    asm volatile("ldmatrix.sync.aligned.m8n8.x4.shared.b16 {%0,%1,%2,%3}, [%4];"
                 : "=r"(r[0]), "=r"(r[1]), "=r"(r[2]), "=r"(r[3]) : "r"(addr));
}
__device__ __forceinline__ void mma_f16(float4& c, const uint32_t a[4], const uint32_t b0, const uint32_t b1) {
    asm volatile(
        "mma.sync.aligned.m16n8k16.row.col.f32.f16.f16.f32 "
        "{%0,%1,%2,%3}, {%4,%5,%6,%7}, {%8,%9}, {%0,%1,%2,%3};"
        : "+f"(c.x), "+f"(c.y), "+f"(c.z), "+f"(c.w)
        : "r"(a[0]), "r"(a[1]), "r"(a[2]), "r"(a[3]), "r"(b0), "r"(b1));
}

__device__ __forceinline__ void st2(float* p, float x, float y)  { *(float2*)p = make_float2(x, y); }
__device__ __forceinline__ void st2(__half* p, float x, float y) { *(__half2*)p = __floats2half2_rn(x, y); }
__device__ __forceinline__ float2 ld2(const float* p)  { return *(const float2*)p; }
__device__ __forceinline__ float2 ld2(const __half* p) { return __half22float2(*(const __half2*)p); }

__device__ __forceinline__ void cvt8(const float* s, __half* d) {
    const float4 a = *(const float4*)s;
    const float4 b = *(const float4*)(s + 4);
    __half2 h[4];
    h[0] = __floats2half2_rn(a.x, a.y);
    h[1] = __floats2half2_rn(a.z, a.w);
    h[2] = __floats2half2_rn(b.x, b.y);
    h[3] = __floats2half2_rn(b.z, b.w);
    *(uint2*)d       = *(uint2*)&h[0];
    *(uint2*)(d + 4) = *(uint2*)&h[2];
}

// ---------------- merged weight conversion (launch 0) ----------------
__global__ __launch_bounds__(256)
void cvtall_k(const float* __restrict__ wqkv, const float* __restrict__ wo,
              const float* __restrict__ w1,   const float* __restrict__ w2)
{
    int i = blockIdx.x * 256 + threadIdx.x;            // 0..N8_WTOT-1 (exact grid)
    const float* src;
    size_t so;
    if      (i < N8_WQKV)                 { src = wqkv; so = i; }
    else if (i < N8_WQKV + N8_WO)         { src = wo;   so = i - N8_WQKV; }
    else if (i < N8_WQKV + N8_WO + N8_W1) { src = w1;   so = i - N8_WQKV - N8_WO; }
    else                                  { src = w2;   so = i - N8_WQKV - N8_WO - N8_W1; }
    cvt8(src + so * 8, g_Wc + (size_t)i * 8);
}

// ---------------- feats+pos conversion into stacked buffer (launch 1) ----------------
__global__ __launch_bounds__(256)
void cvtfp_k(const float* __restrict__ feats, const float* __restrict__ pos)
{
    int i = blockIdx.x * 256 + threadIdx.x;            // 0..N8_FE+N8_PO-1
    if (i >= N8_FE + N8_PO) return;
    if (i < N8_FE) cvt8(feats + (size_t)i * 8, g_FP + (size_t)i * 8);
    else {
        int j = i - N8_FE;
        cvt8(pos + (size_t)j * 8, g_FP + (size_t)2048 * D_ + (size_t)j * 8);
    }
}

// ---------------- layer-0 qkv gather: qkv = fp16(F[frame] + P[w] + bqkv) ----------------
__global__ __launch_bounds__(256)
void qkv0_k(const __half* __restrict__ F, const float* __restrict__ bq,
            __half* __restrict__ qkv)
{
    int idx = blockIdx.x * 256 + threadIdx.x;          // 8 halves per thread
    int n8  = idx % (D3 / 8);
    int row = idx / (D3 / 8);
    int w   = row & 31;
    int seq = row >> 5;
    int t   = seq & (T_ - 1);
    int f   = t + 1 - W_ + w; if (f < 0) f = 0;
    int frame = (seq - t) + f;
    const __half* fr = F + (size_t)frame * D3 + n8 * 8;
    const __half* pr = F + (size_t)(2048 + w) * D3 + n8 * 8;
    const float*  bb = bq + n8 * 8;
    float4 ba = *(const float4*)bb;
    float4 bc = *(const float4*)(bb + 4);
    float2 f0 = ld2(fr),     f1 = ld2(fr + 2), f2 = ld2(fr + 4), f3 = ld2(fr + 6);
    float2 p0 = ld2(pr),     p1 = ld2(pr + 2), p2 = ld2(pr + 4), p3 = ld2(pr + 6);
    __half2 h[4];
    h[0] = __floats2half2_rn(f0.x + p0.x + ba.x, f0.y + p0.y + ba.y);
    h[1] = __floats2half2_rn(f1.x + p1.x + ba.z, f1.y + p1.y + ba.w);
    h[2] = __floats2half2_rn(f2.x + p2.x + bc.x, f2.y + p2.y + bc.y);
    h[3] = __floats2half2_rn(f3.x + p3.x + bc.z, f3.y + p3.y + bc.w);
    __half* dst = qkv + (size_t)idx * 8;
    *(uint2*)dst       = *(uint2*)&h[0];
    *(uint2*)(dst + 4) = *(uint2*)&h[2];
}

// ---------------- gather w=31 rows of X into compact Xc (2048 x 512) ----------------
__global__ __launch_bounds__(256)
void gather31_k(const __half* __restrict__ X, __half* __restrict__ Xc)
{
    int idx = blockIdx.x * 256 + threadIdx.x;
    int d8  = idx & 63;
    int seq = idx >> 6;
    const __half* src = X + ((size_t)(seq * W_ + (W_ - 1))) * D_ + d8 * 8;
    __half* dst = Xc + (size_t)seq * D_ + d8 * 8;
    *(uint2*)dst       = *(const uint2*)src;
    *(uint2*)(dst + 4) = *(const uint2*)(src + 4);
}

// ---------------- fp16 mma.sync GEMM (128x128 tile, BK=64, 3-stage, 1 barrier/chunk) -----------
// WIN=1: residual computed on the fly as feats[frame(m)][n] + pos[w(m)][n] (fp32 inputs).
template<int RELU, int WIN, typename TC, typename TR>
__global__ __launch_bounds__(256, 2)
void hgemm_k(const __half* __restrict__ A, const __half* __restrict__ Bw,
             const float* __restrict__ bias, const TR* __restrict__ resid,
             const float* __restrict__ pos,
             TC* __restrict__ C, int M, int N, int K)
{
    extern __shared__ __half sh[];
    const uint32_t sm0 = smem_u32(sh);

    const int tid  = threadIdx.x;
    const int lane = tid & 31;
    const int wid  = tid >> 5;
    const int wm   = wid >> 2;
    const int wn   = wid & 3;
    const int l4   = lane >> 2;
    const int lm   = lane & 3;
    const int n0   = blockIdx.x * 128;
    const int m0   = blockIdx.y * 128;

    const int row0 = tid >> 3;
    const int prt0 = tid & 7;
    const __half* Au = A  + (size_t)(m0 + row0) * K + prt0 * 8;
    const __half* Bu = Bw + (size_t)(n0 + row0) * K + prt0 * 8;
    const uint32_t du = (uint32_t)(row0 * RS + prt0 * 8) * 2;

    auto stage = [&](int c) {
        uint32_t base = sm0 + (uint32_t)(c % NSTAGE) * STG;
        const size_t ko = (size_t)c * BKH;
#pragma unroll
        for (int i = 0; i < 4; i++) {
            cp16(base + du + i * 32 * RS * 2,       Au + (size_t)(i * 32) * K + ko);
            cp16(base + CHB + du + i * 32 * RS * 2, Bu + (size_t)(i * 32) * K + ko);
        }
        cp_commit();
    };

    const int rA   = lane & 15;
    const int kofA = (lane >> 4) * 8;
    const int rB   = lane & 7;
    const int kofB = ((lane >> 3) & 1) * 8;
    const int whB  = (lane >> 4) * 8;

    const uint32_t aoffs = (uint32_t)((wm * 64 + rA) * RS + kofA) * 2;
    const uint32_t boffs = (uint32_t)CHB + (uint32_t)((wn * 32 + whB + rB) * RS + kofB) * 2;

    float4 acc[4][4];
#pragma unroll
    for (int i = 0; i < 4; i++)
#pragma unroll
        for (int j = 0; j < 4; j++) acc[i][j] = make_float4(0.f, 0.f, 0.f, 0.f);

    const int nchunk = K / BKH;
    stage(0); stage(1);

    uint32_t af[2][4][4], bf[2][2][4];

    for (int c = 0; c < nchunk; c++) {
        if (c + 1 < nchunk) cp_wait1();
        else                cp_wait0();
        __syncthreads();
        if (c + 2 < nchunk) stage(c + 2);

        const uint32_t base = sm0 + (uint32_t)(c % NSTAGE) * STG;

#pragma unroll
        for (int mt = 0; mt < 4; mt++)
            ldm_x4(af[0][mt], base + aoffs + (uint32_t)(mt * 16 * RS) * 2);
#pragma unroll
        for (int ntp = 0; ntp < 2; ntp++)
            ldm_x4(bf[0][ntp], base + boffs + (uint32_t)(ntp * 16 * RS) * 2);

#pragma unroll
        for (int ks = 0; ks < 4; ks++) {
            const int cur = ks & 1, nxt = cur ^ 1;
            if (ks < 3) {
                const uint32_t ko = (uint32_t)((ks + 1) * 16) * 2;
#pragma unroll
                for (int mt = 0; mt < 4; mt++)
                    ldm_x4(af[nxt][mt], base + aoffs + (uint32_t)(mt * 16 * RS) * 2 + ko);
#pragma unroll
                for (int ntp = 0; ntp < 2; ntp++)
                    ldm_x4(bf[nxt][ntp], base + boffs + (uint32_t)(ntp * 16 * RS) * 2 + ko);
            }
#pragma unroll
            for (int mt = 0; mt < 4; mt++)
#pragma unroll
                for (int nt = 0; nt < 4; nt++)
                    mma_f16(acc[mt][nt], af[cur][mt],
                            bf[cur][nt >> 1][(nt & 1) * 2], bf[cur][nt >> 1][(nt & 1) * 2 + 1]);
        }
    }

    __syncthreads();

    auto winres = [&](int mm, int nn) -> float2 {
        int w = mm & 31, seq = mm >> 5, t = seq & (T_ - 1);
        int f = t + 1 - W_ + w; if (f < 0) f = 0;
        int frame = (seq - t) + f;
        float2 a = ld2((const float*)resid + (size_t)frame * D_ + nn);
        float2 p = ld2(pos + (size_t)w * D_ + nn);
        return make_float2(a.x + p.x, a.y + p.y);
    };

#pragma unroll
    for (int mt = 0; mt < 4; mt++) {
        const int m = m0 + wm * 64 + mt * 16 + l4;
#pragma unroll
        for (int nt = 0; nt < 4; nt++) {
            const int n = n0 + wn * 32 + nt * 8 + lm * 2;
            float4 cc = acc[mt][nt];
            float2 bv = *(const float2*)(bias + n);
            cc.x += bv.x; cc.y += bv.y;
            cc.z += bv.x; cc.w += bv.y;
            if (WIN) {
                float2 r0 = winres(m, n);
                float2 r1 = winres(m + 8, n);
                cc.x += r0.x; cc.y += r0.y;
                cc.z += r1.x; cc.w += r1.y;
            } else if (resid) {
                float2 r0 = ld2(resid + (size_t)m * N + n);
                float2 r1 = ld2(resid + (size_t)(m + 8) * N + n);
                cc.x += r0.x; cc.y += r0.y;
                cc.z += r1.x; cc.w += r1.y;
            }
            if (RELU) {
                cc.x = fmaxf(cc.x, 0.f); cc.y = fmaxf(cc.y, 0.f);
                cc.z = fmaxf(cc.z, 0.f); cc.w = fmaxf(cc.w, 0.f);
            }
            st2(C + (size_t)m * N + n,       cc.x, cc.y);
            st2(C + (size_t)(m + 8) * N + n, cc.z, cc.w);
        }
    }
}

// ---------------- attention (layers 0-2): one warp per (seq, head); packed-half smem ------------
__global__ __launch_bounds__(32)
void attn_k(const __half* __restrict__ qkv, __half* __restrict__ ctx)
{
    const int sh   = blockIdx.x;
    const int seq  = sh >> 3;
    const int h    = sh & 7;
    const int lane = threadIdx.x;

    __shared__ uint2 ks[W_][16], vs[W_][16];      // 4 halves per slot -> 4KB each

    const __half* base = qkv + (size_t)seq * W_ * D3 + h * DH;

#pragma unroll
    for (int i = 0; i < 16; i++) {
        int idx = i * 32 + lane;
        int row = idx >> 4, c4 = idx & 15;
        const __half* src = base + (size_t)row * D3 + c4 * 4;
        ks[row][c4] = *(const uint2*)(src + 512);
        vs[row][c4] = *(const uint2*)(src + 1024);
    }
    float4 q[16];
    {
        const __half* qr = base + (size_t)lane * D3;
#pragma unroll
        for (int i = 0; i < 16; i++) {
            float2 a = ld2(qr + i * 4);
            float2 b = ld2(qr + i * 4 + 2);
            q[i] = make_float4(a.x, a.y, b.x, b.y);
        }
    }
    __syncwarp();

    float sc[W_];
#pragma unroll
    for (int c = 0; c < W_; c++) {
        float s = 0.f;
#pragma unroll
        for (int e = 0; e < 16; e++) {
            uint2 kk = ks[c][e];                   // broadcast LDS.64
            float2 k0 = __half22float2(*(__half2*)&kk.x);
            float2 k1 = __half22float2(*(__half2*)&kk.y);
            s += q[e].x * k0.x + q[e].y * k0.y + q[e].z * k1.x + q[e].w * k1.y;
        }
        sc[c] = (c <= lane) ? s * 0.125f : -1e30f;
    }

    float mx = -1e30f;
#pragma unroll
    for (int c = 0; c < W_; c++) mx = fmaxf(mx, sc[c]);
    float sum = 0.f;
#pragma unroll
    for (int c = 0; c < W_; c++) { float e = expf(sc[c] - mx); sc[c] = e; sum += e; }
    float inv = 1.f / sum;

    float4 acc[16];
#pragma unroll
    for (int e = 0; e < 16; e++) acc[e] = make_float4(0.f, 0.f, 0.f, 0.f);
#pragma unroll
    for (int c = 0; c < W_; c++) {
        float p = sc[c] * inv;
#pragma unroll
        for (int e = 0; e < 16; e++) {
            uint2 vv = vs[c][e];
            float2 v0 = __half22float2(*(__half2*)&vv.x);
            float2 v1 = __half22float2(*(__half2*)&vv.y);
            acc[e].x += p * v0.x; acc[e].y += p * v0.y;
            acc[e].z += p * v1.x; acc[e].w += p * v1.y;
        }
    }

    __half* dst = ctx + ((size_t)seq * W_ + lane) * D_ + h * DH;
#pragma unroll
    for (int e = 0; e < 16; e++) {
        *(__half2*)(dst + e * 4)     = __floats2half2_rn(acc[e].x, acc[e].y);
        *(__half2*)(dst + e * 4 + 2) = __floats2half2_rn(acc[e].z, acc[e].w);
    }
}

// ---------------- layer-3 attention: only row w=31; kv row stride 1024 ----------------
__global__ __launch_bounds__(32)
void attn3_k(const __half* __restrict__ kv, const __half* __restrict__ qc,
             __half* __restrict__ ctxc)
{
    const int sh   = blockIdx.x;
    const int seq  = sh >> 3;
    const int h    = sh & 7;
    const int lane = threadIdx.x;

    __shared__ float qs[DH];
    __shared__ float ps[W_];

    const __half* qp = qc + (size_t)seq * D_ + h * DH;
    float2 qv = ld2(qp + lane * 2);
    qs[lane * 2] = qv.x; qs[lane * 2 + 1] = qv.y;
    __syncwarp();

    const __half* kp = kv + ((size_t)seq * W_ + lane) * 1024 + h * DH;
    float s = 0.f;
#pragma unroll
    for (int e = 0; e < DH; e += 2) {
        float2 kk = ld2(kp + e);
        s += qs[e] * kk.x + qs[e + 1] * kk.y;
    }
    s *= 0.125f;

    float mx = s;
#pragma unroll
    for (int o = 16; o; o >>= 1) mx = fmaxf(mx, __shfl_xor_sync(0xffffffffu, mx, o));
    float e = expf(s - mx), sum = e;
#pragma unroll
    for (int o = 16; o; o >>= 1) sum += __shfl_xor_sync(0xffffffffu, sum, o);
    ps[lane] = e / sum;
    __syncwarp();

    float a0 = 0.f, a1 = 0.f;
    const __half* vp = kv + (size_t)seq * W_ * 1024 + 512 + h * DH + lane * 2;
#pragma unroll
    for (int c = 0; c < W_; c++) {
        float2 vv = ld2(vp + (size_t)c * 1024);
        a0 += ps[c] * vv.x; a1 += ps[c] * vv.y;
    }
    *(__half2*)(ctxc + (size_t)seq * D_ + h * DH + lane * 2) = __floats2half2_rn(a0, a1);
}

// ---------------- LayerNorm: warp per row; fp32 in -> fp16 out ----------------
__global__ __launch_bounds__(256)
void ln_k(const float* __restrict__ in, const float* __restrict__ g,
          const float* __restrict__ b, __half* __restrict__ out)
{
    const int row  = blockIdx.x * 8 + (threadIdx.x >> 5);
    const int lane = threadIdx.x & 31;
    const float* x = in + (size_t)row * D_ + lane * 4;

    float4 v[4];
#pragma unroll
    for (int i = 0; i < 4; i++) v[i] = *(const float4*)(x + i * 128);

    float s = 0.f, sq = 0.f;
#pragma unroll
    for (int i = 0; i < 4; i++) {
        s  += v[i].x + v[i].y + v[i].z + v[i].w;
        sq += v[i].x * v[i].x + v[i].y * v[i].y + v[i].z * v[i].z + v[i].w * v[i].w;
    }
#pragma unroll
    for (int off = 16; off; off >>= 1) {
        s  += __shfl_xor_sync(0xffffffffu, s,  off);
        sq += __shfl_xor_sync(0xffffffffu, sq, off);
    }
    const float mean = s * (1.f / D_);
    const float rstd = rsqrtf(sq * (1.f / D_) - mean * mean + 1e-5f);

    __half* o = out + (size_t)row * D_ + lane * 4;
#pragma unroll
    for (int i = 0; i < 4; i++) {
        float4 g4 = *(const float4*)(g + lane * 4 + i * 128);
        float4 b4 = *(const float4*)(b + lane * 4 + i * 128);
        float rx = (v[i].x - mean) * rstd * g4.x + b4.x;
        float ry = (v[i].y - mean) * rstd * g4.y + b4.y;
        float rz = (v[i].z - mean) * rstd * g4.z + b4.z;
        float rw = (v[i].w - mean) * rstd * g4.w + b4.w;
        *(__half2*)(o + i * 128)     = __floats2half2_rn(rx, ry);
        *(__half2*)(o + i * 128 + 2) = __floats2half2_rn(rz, rw);
    }
}

// ---------------- head: logits (B,T,A) then values (B,T); reads compact Xc ----------------
__global__ __launch_bounds__(256)
void head_k(const __half* __restrict__ xc, const float* __restrict__ Wp,
            const float* __restrict__ bp, const float* __restrict__ Wv,
            const float* __restrict__ bv, float* __restrict__ out)
{
    const int seq = blockIdx.x;
    __shared__ float tok[D_];
    const int tid = threadIdx.x;
    const __half* src = xc + (size_t)seq * D_;
    float2 f = ld2(src + tid * 2);
    tok[tid * 2] = f.x; tok[tid * 2 + 1] = f.y;
    __syncthreads();
    int wid = tid >> 5, lane = tid & 31;
    if (wid < 7) {
        const float* wrow = (wid < 6) ? (Wp + wid * D_) : Wv;
        float s = 0.f;
        for (int i = lane; i < D_; i += 32) s += tok[i] * wrow[i];
#pragma unroll
        for (int off = 16; off; off >>= 1) s += __shfl_down_sync(0xffffffffu, s, off);
        if (lane == 0) {
            if (wid < 6) out[(size_t)seq * A_ + wid] = s + bp[wid];
            else         out[(size_t)NSEQ * A_ + seq] = s + bv[0];
        }
    }
}

// ---------------- launch ----------------
extern "C" void kernel_launch(void* const* d_in, const int* in_sizes, int n_in,
                              void* d_out, int out_size)
{
    const float* feats = (const float*)d_in[0];
    const float* pos   = (const float*)d_in[1];
    const float* Wqkv  = (const float*)d_in[2];
    const float* bqkv  = (const float*)d_in[3];
    const float* Wo    = (const float*)d_in[4];
    const float* bo    = (const float*)d_in[5];
    const float* ln1g  = (const float*)d_in[6];
    const float* ln1b  = (const float*)d_in[7];
    const float* W1    = (const float*)d_in[8];
    const float* b1    = (const float*)d_in[9];
    const float* W2    = (const float*)d_in[10];
    const float* b2    = (const float*)d_in[11];
    const float* ln2g  = (const float*)d_in[12];
    const float* ln2b  = (const float*)d_in[13];
    const float* Wp    = (const float*)d_in[14];
    const float* bp    = (const float*)d_in[15];
    const float* Wv    = (const float*)d_in[16];
    const float* bv    = (const float*)d_in[17];
    float* out = (float*)d_out;

    __half *X, *QKV, *Hb, *Wc, *FP, *F;
    float *PRE, *ZB;
    cudaGetSymbolAddress((void**)&X,   g_X);
    cudaGetSymbolAddress((void**)&QKV, g_QKV);
    cudaGetSymbolAddress((void**)&Hb,  g_H);
    cudaGetSymbolAddress((void**)&PRE, g_PRE);
    cudaGetSymbolAddress((void**)&Wc,  g_Wc);
    cudaGetSymbolAddress((void**)&FP,  g_FP);
    cudaGetSymbolAddress((void**)&F,   g_F);
    cudaGetSymbolAddress((void**)&ZB,  g_zerob);

    // layer-3 compact buffers (reuse scratch whose producers are done by then)
    __half* Xc   = FP;    // 2048 x 512
    __half* Qc   = F;     // 2048 x 512
    __half* CTXc = Hb;    // 2048 x 512
    __half* HIDc = Hb;    // 2048 x 2048 (after CTXc consumed)
    __half* KV   = QKV;   // 65536 x 1024

    static int attr_done = 0;
    if (!attr_done) {
        cudaFuncSetAttribute((const void*)hgemm_k<0,0,float,__half>,  cudaFuncAttributeMaxDynamicSharedMemorySize, HGEMM_SMEM);
        cudaFuncSetAttribute((const void*)hgemm_k<0,0,__half,__half>, cudaFuncAttributeMaxDynamicSharedMemorySize, HGEMM_SMEM);
        cudaFuncSetAttribute((const void*)hgemm_k<1,0,__half,__half>, cudaFuncAttributeMaxDynamicSharedMemorySize, HGEMM_SMEM);
        cudaFuncSetAttribute((const void*)hgemm_k<0,1,float,float>,   cudaFuncAttributeMaxDynamicSharedMemorySize, HGEMM_SMEM);
        attr_done = 1;
    }

    // launch 0: all weights -> fp16
    cvtall_k<<<N8_WTOT / 256, 256>>>(Wqkv, Wo, W1, W2);
    // launch 1: feats+pos -> stacked fp16 buffer
    cvtfp_k<<<(N8_FE + N8_PO + 255) / 256, 256>>>(feats, pos);

    // ---- layer 0 (factored QKV) ----
    // launch 2: stacked [feats;pos] @ Wqkv0^T  (M=2176)
    hgemm_k<0,0,__half,__half><<<dim3(D3 / 128, MFP / 128), 256, HGEMM_SMEM>>>(
        FP, Wc + OFF_WQKV, ZB, nullptr, nullptr, F, MFP, D3, D_);
    // launch 3: qkv = F[frame] + P[w] + bqkv
    qkv0_k<<<(MROWS * D3 / 8) / 256, 256>>>(F, bqkv, QKV);
    // launch 4: attention
    attn_k<<<NSEQ * H_, 32>>>(QKV, Hb);
    // launch 5 (PROFILED): preLN1 = (feats[frame]+pos[w]) + ctx @ Wo0^T + bo0
    hgemm_k<0,1,float,float><<<dim3(D_ / 128, MROWS / 128), 256, HGEMM_SMEM>>>(
        Hb, Wc + OFF_WO, bo, feats, pos, PRE, MROWS, D_, D_);
    ln_k<<<MROWS / 8, 256>>>(PRE, ln1g, ln1b, X);
    hgemm_k<1,0,__half,__half><<<dim3(DF / 128, MROWS / 128), 256, HGEMM_SMEM>>>(
        X, Wc + OFF_W1, b1, nullptr, nullptr, Hb, MROWS, DF, D_);
    hgemm_k<0,0,float,__half><<<dim3(D_ / 128, MROWS / 128), 256, HGEMM_SMEM>>>(
        Hb, Wc + OFF_W2, b2, X, nullptr, PRE, MROWS, D_, DF);
    ln_k<<<MROWS / 8, 256>>>(PRE, ln2g, ln2b, X);

    // ---- layers 1..2: full pipeline ----
    for (int i = 1; i < L_ - 1; i++) {
        hgemm_k<0,0,__half,__half><<<dim3(D3 / 128, MROWS / 128), 256, HGEMM_SMEM>>>(
            X, Wc + OFF_WQKV + (size_t)i * D3 * D_, bqkv + i * D3, nullptr, nullptr, QKV, MROWS, D3, D_);
        attn_k<<<NSEQ * H_, 32>>>(QKV, Hb);
        hgemm_k<0,0,float,__half><<<dim3(D_ / 128, MROWS / 128), 256, HGEMM_SMEM>>>(
            Hb, Wc + OFF_WO + (size_t)i * D_ * D_, bo + i * D_, X, nullptr, PRE, MROWS, D_, D_);
        ln_k<<<MROWS / 8, 256>>>(PRE, ln1g + i * D_, ln1b + i * D_, X);
        hgemm_k<1,0,__half,__half><<<dim3(DF / 128, MROWS / 128), 256, HGEMM_SMEM>>>(
            X, Wc + OFF_W1 + (size_t)i * DF * D_, b1 + i * DF, nullptr, nullptr, Hb, MROWS, DF, D_);
        hgemm_k<0,0,float,__half><<<dim3(D_ / 128, MROWS / 128), 256, HGEMM_SMEM>>>(
            Hb, Wc + OFF_W2 + (size_t)i * D_ * DF, b2 + i * D_, X, nullptr, PRE, MROWS, D_, DF);
        ln_k<<<MROWS / 8, 256>>>(PRE, ln2g + i * D_, ln2b + i * D_, X);
    }

    // ---- layer 3: only the w=31 rows survive into the head ----
    {
        const int i = L_ - 1;    // 3
        hgemm_k<0,0,__half,__half><<<dim3(1024 / 128, MROWS / 128), 256, HGEMM_SMEM>>>(
            X, Wc + OFF_WQKV + (size_t)i * D3 * D_ + (size_t)D_ * D_,
            bqkv + i * D3 + D_, nullptr, nullptr, KV, MROWS, 1024, D_);
        gather31_k<<<(NSEQ * 64) / 256, 256>>>(X, Xc);
        hgemm_k<0,0,__half,__half><<<dim3(D_ / 128, NSEQ / 128), 256, HGEMM_SMEM>>>(
            Xc, Wc + OFF_WQKV + (size_t)i * D3 * D_, bqkv + i * D3, nullptr, nullptr, Qc, NSEQ, D_, D_);
        attn3_k<<<NSEQ * H_, 32>>>(KV, Qc, CTXc);
        hgemm_k<0,0,float,__half><<<dim3(D_ / 128, NSEQ / 128), 256, HGEMM_SMEM>>>(
            CTXc, Wc + OFF_WO + (size_t)i * D_ * D_, bo + i * D_, Xc, nullptr, PRE, NSEQ, D_, D_);
        ln_k<<<NSEQ / 8, 256>>>(PRE, ln1g + i * D_, ln1b + i * D_, Xc);
        hgemm_k<1,0,__half,__half><<<dim3(DF / 128, NSEQ / 128), 256, HGEMM_SMEM>>>(
            Xc, Wc + OFF_W1 + (size_t)i * DF * D_, b1 + i * DF, nullptr, nullptr, HIDc, NSEQ, DF, D_);
        hgemm_k<0,0,float,__half><<<dim3(D_ / 128, NSEQ / 128), 256, HGEMM_SMEM>>>(
            HIDc, Wc + OFF_W2 + (size_t)i * D_ * DF, b2 + i * D_, Xc, nullptr, PRE, NSEQ, D_, DF);
        ln_k<<<NSEQ / 8, 256>>>(PRE, ln2g + i * D_, ln2b + i * D_, Xc);
    }

    head_k<<<NSEQ, 256>>>(Xc, Wp, bp, Wv, bv, out);
}